// round 1
// baseline (speedup 1.0000x reference)
#include <cuda_runtime.h>
#include <math.h>

#define NN 20000
#define NE 200000
#define CC 64
#define HH 4
#define HCC 256

// ---------------- scratch (device globals; allocation-free rule) ----------------
__device__ float    g_h[NN*CC];      // node features [N,64]
__device__ float    g_f[NE*CC];      // edge features [E,64]
__device__ float    g_ni[NN*HCC];    // h @ Wni   [N,256]
__device__ float    g_nj[NN*HCC];    // h @ Wnj   [N,256]
__device__ float    g_hp[NN*HCC];    // h @ Wnode + bnode [N,256]
__device__ float    g_fw[NE*HCC];    // f @ Wfij  [E,256]
__device__ float    g_score[NE*HH];  // scores, then softmax weights [E,4]
__device__ unsigned g_smax[NN*HH];   // encoded segment max [N,4]
__device__ float    g_denom[NN*HH];  // softmax denominators [N,4]
__device__ float    g_hnew[NN*HCC];  // aggregated messages [N,4,64]

// order-preserving float<->uint map for atomicMax on floats
__device__ __forceinline__ unsigned encf(float x){
    unsigned u = __float_as_uint(x);
    return (u & 0x80000000u) ? ~u : (u | 0x80000000u);
}
__device__ __forceinline__ float decf(unsigned e){
    unsigned u = (e & 0x80000000u) ? (e & 0x7FFFFFFFu) : ~e;
    return __uint_as_float(u);
}

// ---------------- per-layer zero init ----------------
__global__ void k_layer_init(){
    int i  = blockIdx.x*blockDim.x + threadIdx.x;
    int st = gridDim.x*blockDim.x;
    for (int j=i; j<NN*HCC; j+=st) g_hnew[j] = 0.f;
    for (int j=i; j<NN*HH;  j+=st){ g_denom[j] = 0.f; g_smax[j] = 0u; }
}

// ---------------- generic small GEMM: out[rows,64] = A[rows,K] @ W[K,64] + bias ----------------
__global__ __launch_bounds__(256) void small_gemm(
    const float* __restrict__ A, const float* __restrict__ W,
    const float* __restrict__ bias, float* __restrict__ out, int rows, int K){
    __shared__ float sW[65*64];
    __shared__ float sA[4*65];
    for (int i=threadIdx.x; i<K*64; i+=256) sW[i] = W[i];
    __syncthreads();
    const int col = threadIdx.x & 63;
    const int rl  = threadIdx.x >> 6;
    const float b = bias[col];
    for (int base = blockIdx.x*4; base < rows; base += gridDim.x*4){
        for (int i=threadIdx.x; i<4*K; i+=256){
            int r = i / K, k = i - r*K;
            sA[i] = (base + r < rows) ? A[(base+r)*K + k] : 0.f;
        }
        __syncthreads();
        const int row = base + rl;
        if (row < rows){
            float acc = b;
            for (int k=0;k<K;k++) acc += sA[rl*K + k]*sW[k*64 + col];
            out[row*64 + col] = acc;
        }
        __syncthreads();
    }
}

// ---------------- big GEMM: out[rows,256] = A[rows,64] @ W[64,256] (+bias) ----------------
// block tile 64 rows x 128 cols, 256 threads, 4x8 register tile per thread
__global__ __launch_bounds__(256) void gemm_64_256(
    const float* __restrict__ A, const float* __restrict__ W,
    const float* __restrict__ bias, float* __restrict__ out, int rows){
    __shared__ float sA[64*64];    // [r][k]
    __shared__ float sW[64*128];   // [k][c_local]
    const int tid  = threadIdx.x;
    const int row0 = blockIdx.x*64;
    const int cb   = blockIdx.y*128;

    const float4* A4  = reinterpret_cast<const float4*>(A);
    float4*       sA4 = reinterpret_cast<float4*>(sA);
    #pragma unroll
    for (int it=0; it<4; it++){
        int i = tid + it*256;
        int r = i >> 4, k4 = i & 15;
        float4 v = make_float4(0.f,0.f,0.f,0.f);
        if (row0 + r < rows) v = A4[(row0+r)*16 + k4];
        sA4[r*16 + k4] = v;
    }
    const float4* W4  = reinterpret_cast<const float4*>(W);
    float4*       sW4 = reinterpret_cast<float4*>(sW);
    #pragma unroll
    for (int it=0; it<8; it++){
        int i = tid + it*256;
        int k = i >> 5, c4 = i & 31;
        sW4[k*32 + c4] = W4[k*64 + (cb>>2) + c4];
    }
    __syncthreads();

    const int ty = tid >> 4, tx = tid & 15;
    const int r0 = ty*4,  c0 = tx*8;
    float acc[4][8];
    #pragma unroll
    for (int i=0;i<4;i++)
        #pragma unroll
        for (int j=0;j<8;j++) acc[i][j] = 0.f;

    #pragma unroll 8
    for (int k=0;k<64;k++){
        float av[4];
        av[0] = sA[(r0+0)*64+k];
        av[1] = sA[(r0+1)*64+k];
        av[2] = sA[(r0+2)*64+k];
        av[3] = sA[(r0+3)*64+k];
        float4 w0 = *reinterpret_cast<const float4*>(&sW[k*128 + c0]);
        float4 w1 = *reinterpret_cast<const float4*>(&sW[k*128 + c0 + 4]);
        float wv[8] = {w0.x,w0.y,w0.z,w0.w,w1.x,w1.y,w1.z,w1.w};
        #pragma unroll
        for (int i=0;i<4;i++)
            #pragma unroll
            for (int j=0;j<8;j++) acc[i][j] += av[i]*wv[j];
    }

    float bv[8];
    #pragma unroll
    for (int j=0;j<8;j++) bv[j] = bias ? bias[cb + c0 + j] : 0.f;

    #pragma unroll
    for (int i=0;i<4;i++){
        int r = row0 + r0 + i;
        if (r < rows){
            float4 o0 = make_float4(acc[i][0]+bv[0], acc[i][1]+bv[1], acc[i][2]+bv[2], acc[i][3]+bv[3]);
            float4 o1 = make_float4(acc[i][4]+bv[4], acc[i][5]+bv[5], acc[i][6]+bv[6], acc[i][7]+bv[7]);
            float4* op = reinterpret_cast<float4*>(out + r*256 + cb + c0);
            op[0] = o0; op[1] = o1;
        }
    }
}

// ---------------- edge stage A: fo = fw + ni[src] + nj[dst] + bias; scores; segment max;
//                  and new f = elu(inorm(mean over heads of fo)) ----------------
__global__ __launch_bounds__(256) void edge_a(
    const int* __restrict__ src, const int* __restrict__ dst,
    const float* __restrict__ bias_e, const float* __restrict__ attn){
    const int e = blockIdx.x, t = threadIdx.x;
    const int s = src[e], d = dst[e];
    float fo = g_fw[e*256+t] + g_ni[s*256+t] + g_nj[d*256+t] + bias_e[t];
    float el = fo > 0.f ? fo : 0.01f*fo;           // leaky_relu 0.01
    float sc = el * attn[t];                       // attn laid out [H,C] == 256
    #pragma unroll
    for (int o=16;o>0;o>>=1) sc += __shfl_down_sync(0xffffffffu, sc, o);

    __shared__ float sFO[256];
    __shared__ float sRed[8];
    __shared__ float sStat[2];
    sFO[t] = fo;
    const int w = t>>5, lane = t&31;
    if (lane==0) sRed[w] = sc;
    __syncthreads();

    if (t < 4){
        float sh = sRed[2*t] + sRed[2*t+1];        // per-head score
        g_score[e*4+t] = sh;
        atomicMax(&g_smax[d*4+t], encf(sh));
    }
    float fm = 0.f;
    if (t < 64) fm = 0.25f*(sFO[t] + sFO[t+64] + sFO[t+128] + sFO[t+192]);
    __syncthreads();   // protects sRed reuse below

    float s1 = fm, s2 = fm*fm;
    if (t < 64){
        #pragma unroll
        for (int o=16;o>0;o>>=1){
            s1 += __shfl_down_sync(0xffffffffu, s1, o);
            s2 += __shfl_down_sync(0xffffffffu, s2, o);
        }
        if (lane==0){ sRed[w] = s1; sRed[4+w] = s2; }
    }
    __syncthreads();
    if (t == 0){
        float m   = (sRed[0]+sRed[1]) * 0.015625f;
        float var = (sRed[4]+sRed[5]) * 0.015625f - m*m;
        sStat[0] = m;
        sStat[1] = rsqrtf(var + 1e-5f);
    }
    __syncthreads();
    if (t < 64){
        float v = (fm - sStat[0]) * sStat[1];
        g_f[e*64+t] = v > 0.f ? v : expm1f(v);     // elu
    }
}

// ---------------- edge stage B: w = exp(score - smax[dst]); denom += w ----------------
__global__ __launch_bounds__(256) void edge_b(const int* __restrict__ dst){
    int idx = blockIdx.x*256 + threadIdx.x;
    if (idx >= NE*4) return;
    int e = idx >> 2, hh = idx & 3;
    int d = dst[e];
    float sm = decf(g_smax[d*4 + hh]);
    float w  = expf(g_score[idx] - sm);
    g_score[idx] = w;
    atomicAdd(&g_denom[d*4 + hh], w);
}

// ---------------- edge stage C: hnew[dst] += hp[src] * (w/denom[dst]) ----------------
__global__ __launch_bounds__(64) void edge_c(const int* __restrict__ src, const int* __restrict__ dst){
    const int e = blockIdx.x, t = threadIdx.x;     // t covers 4 cols each
    const int s = src[e], d = dst[e];
    const int hh = t >> 4;                          // head of columns t*4..t*4+3
    float a = g_score[e*4 + hh] / g_denom[d*4 + hh];
    float4 hp = *reinterpret_cast<const float4*>(&g_hp[s*256 + t*4]);
    float* dp = &g_hnew[d*256 + t*4];
    atomicAdd(dp+0, hp.x*a);
    atomicAdd(dp+1, hp.y*a);
    atomicAdd(dp+2, hp.z*a);
    atomicAdd(dp+3, hp.w*a);
}

// ---------------- node update: h = elu(inorm(mean over heads of hnew)) ----------------
__global__ __launch_bounds__(64) void node_upd(){
    const int n = blockIdx.x, t = threadIdx.x;     // 64 threads = channels
    float v = 0.25f*(g_hnew[n*256+t] + g_hnew[n*256+64+t] +
                     g_hnew[n*256+128+t] + g_hnew[n*256+192+t]);
    float s1 = v, s2 = v*v;
    #pragma unroll
    for (int o=16;o>0;o>>=1){
        s1 += __shfl_down_sync(0xffffffffu, s1, o);
        s2 += __shfl_down_sync(0xffffffffu, s2, o);
    }
    __shared__ float sR[4];
    __shared__ float sStat[2];
    const int w = t>>5, lane = t&31;
    if (lane==0){ sR[w] = s1; sR[2+w] = s2; }
    __syncthreads();
    if (t == 0){
        float m   = (sR[0]+sR[1]) * 0.015625f;
        float var = (sR[2]+sR[3]) * 0.015625f - m*m;
        sStat[0] = m;
        sStat[1] = rsqrtf(var + 1e-5f);
    }
    __syncthreads();
    float o = (v - sStat[0]) * sStat[1];
    g_h[n*64+t] = o > 0.f ? o : expm1f(o);
}

// ---------------- host ----------------
extern "C" void kernel_launch(void* const* d_in, const int* in_sizes, int n_in,
                              void* d_out, int out_size){
    (void)in_sizes; (void)n_in; (void)out_size;
    const float* x      = (const float*)d_in[0];
    const float* efeat  = (const float*)d_in[1];
    const int*   src    = (const int*)  d_in[2];
    const int*   dst    = (const int*)  d_in[3];
    const float* Wn0    = (const float*)d_in[4];
    const float* bn0    = (const float*)d_in[5];
    const float* We0    = (const float*)d_in[6];
    const float* be0    = (const float*)d_in[7];
    const float* Wnode  = (const float*)d_in[8];
    const float* bnode  = (const float*)d_in[9];
    const float* Wni    = (const float*)d_in[10];
    const float* Wnj    = (const float*)d_in[11];
    const float* Wfij   = (const float*)d_in[12];
    const float* attn   = (const float*)d_in[13];
    const float* bias_e = (const float*)d_in[14];
    const float* Wf     = (const float*)d_in[15];
    const float* bf     = (const float*)d_in[16];

    float *p_h, *p_f, *p_ni, *p_nj, *p_hp, *p_fw;
    cudaGetSymbolAddress((void**)&p_h,  g_h);
    cudaGetSymbolAddress((void**)&p_f,  g_f);
    cudaGetSymbolAddress((void**)&p_ni, g_ni);
    cudaGetSymbolAddress((void**)&p_nj, g_nj);
    cudaGetSymbolAddress((void**)&p_hp, g_hp);
    cudaGetSymbolAddress((void**)&p_fw, g_fw);

    // initial embeddings
    small_gemm<<<5000, 256>>>(x,     Wn0, bn0, p_h, NN, 65);
    small_gemm<<<8192, 256>>>(efeat, We0, be0, p_f, NE, 15);

    for (int l=0; l<2; l++){
        k_layer_init<<<2048, 256>>>();
        gemm_64_256<<<dim3(313, 2), 256>>>(p_h, Wni   + l*16384, nullptr,        p_ni, NN);
        gemm_64_256<<<dim3(313, 2), 256>>>(p_h, Wnj   + l*16384, nullptr,        p_nj, NN);
        gemm_64_256<<<dim3(313, 2), 256>>>(p_h, Wnode + l*16384, bnode + l*256,  p_hp, NN);
        gemm_64_256<<<dim3(3125,2), 256>>>(p_f, Wfij  + l*16384, nullptr,        p_fw, NE);
        edge_a<<<NE, 256>>>(src, dst, bias_e + l*256, attn + l*256);
        edge_b<<<(NE*4 + 255)/256, 256>>>(dst);
        edge_c<<<NE, 64>>>(src, dst);
        node_upd<<<NN, 64>>>();
    }

    // final head
    small_gemm<<<5000, 256>>>(p_h, Wf, bf, (float*)d_out, NN, 64);
}

// round 2
// speedup vs baseline: 1.8417x; 1.8417x over previous
#include <cuda_runtime.h>
#include <math.h>

#define NN 20000
#define NE 200000

// ---------------- scratch (device globals; allocation-free rule) ----------------
__device__ __align__(16) float g_h[NN*64];      // node features [N,64]
__device__ __align__(16) float g_f[NE*64];      // edge features [E,64]
__device__ __align__(16) float g_ni[NN*256];    // h @ Wni   [N,256]
__device__ __align__(16) float g_nj[NN*256];    // h @ Wnj   [N,256]
__device__ __align__(16) float g_hp[NN*256];    // h @ Wnode + bnode [N,256]
__device__ __align__(16) float g_fw[NE*256];    // f @ Wfij  [E,256]
__device__ __align__(16) float g_score[NE*4];   // per-edge per-head scores
__device__ int g_rowptr[NN+1];
__device__ int g_cur[NN];                       // counts, then scatter cursor
__device__ int g_eidx[NE];                      // CSR edge index (by dst)

// ---------------- CSR build ----------------
__global__ void k_zero_cnt(){
    int i = blockIdx.x*blockDim.x + threadIdx.x;
    if (i < NN) g_cur[i] = 0;
}
__global__ void k_count(const int* __restrict__ dst){
    int e = blockIdx.x*blockDim.x + threadIdx.x;
    if (e < NE) atomicAdd(&g_cur[dst[e]], 1);
}
__global__ __launch_bounds__(1024) void k_scan(){
    __shared__ int sPart[1024];
    const int t = threadIdx.x;
    const int beg = t*20;
    const int end = (beg+20 < NN) ? beg+20 : NN;
    int s = 0;
    for (int i=beg; i<end; i++) s += g_cur[i];
    sPart[t] = s;
    __syncthreads();
    for (int o=1; o<1024; o<<=1){
        int v = (t >= o) ? sPart[t-o] : 0;
        __syncthreads();
        sPart[t] += v;
        __syncthreads();
    }
    int run = (t==0) ? 0 : sPart[t-1];
    for (int i=beg; i<end; i++){
        int c = g_cur[i];
        g_rowptr[i] = run;
        g_cur[i]    = run;
        run += c;
    }
    if (t == 0) g_rowptr[NN] = NE;
}
__global__ void k_scatter(const int* __restrict__ dst){
    int e = blockIdx.x*blockDim.x + threadIdx.x;
    if (e < NE){
        int p = atomicAdd(&g_cur[dst[e]], 1);
        g_eidx[p] = e;
    }
}

// ---------------- generic small GEMM: out[rows,64] = A[rows,K] @ W[K,64] + bias ----------------
__global__ __launch_bounds__(256) void small_gemm(
    const float* __restrict__ A, const float* __restrict__ W,
    const float* __restrict__ bias, float* __restrict__ out, int rows, int K){
    __shared__ float sW[65*64];
    __shared__ float sA[4*65];
    for (int i=threadIdx.x; i<K*64; i+=256) sW[i] = W[i];
    __syncthreads();
    const int col = threadIdx.x & 63;
    const int rl  = threadIdx.x >> 6;
    const float b = bias[col];
    for (int base = blockIdx.x*4; base < rows; base += gridDim.x*4){
        for (int i=threadIdx.x; i<4*K; i+=256){
            int r = i / K, k = i - r*K;
            sA[i] = (base + r < rows) ? A[(base+r)*K + k] : 0.f;
        }
        __syncthreads();
        const int row = base + rl;
        if (row < rows){
            float acc = b;
            for (int k=0;k<K;k++) acc += sA[rl*K + k]*sW[k*64 + col];
            out[row*64 + col] = acc;
        }
        __syncthreads();
    }
}

// ---------------- big GEMM: out[rows,256] = A[rows,64] @ W[64,256] (+bias) ----------------
// 128x128 block tile, 256 threads, 8x8 register tile, K chunked by 32.
#define SAS 36   // sA row stride (floats); 36*4=144B keeps float4 alignment, 4*36 % 32 != 0
__global__ __launch_bounds__(256) void gemm128(
    const float* __restrict__ A, const float* __restrict__ W,
    const float* __restrict__ bias, float* __restrict__ out, int rows){
    __shared__ float sA[128*SAS];   // [r][k-chunk 32], padded
    __shared__ float sW[32*128];    // [k][c] chunk
    const int tid  = threadIdx.x;
    const int row0 = blockIdx.x*128;
    const int cb   = blockIdx.y*128;
    const int tx = tid & 15, ty = tid >> 4;
    const int r0 = ty*4, c0 = tx*4;

    const float4* A4 = reinterpret_cast<const float4*>(A);
    const float4* W4 = reinterpret_cast<const float4*>(W);

    float acc[8][8];
    #pragma unroll
    for (int i=0;i<8;i++)
        #pragma unroll
        for (int j=0;j<8;j++) acc[i][j] = 0.f;

    for (int kc=0; kc<2; kc++){
        #pragma unroll
        for (int it=0; it<4; it++){
            int idx = it*256 + tid;
            int r = idx >> 3, k4 = idx & 7;
            float4 v = make_float4(0.f,0.f,0.f,0.f);
            if (row0 + r < rows) v = A4[(row0+r)*16 + kc*8 + k4];
            *reinterpret_cast<float4*>(&sA[r*SAS + k4*4]) = v;
        }
        #pragma unroll
        for (int it=0; it<4; it++){
            int idx = it*256 + tid;
            int k = idx >> 5, c4 = idx & 31;
            reinterpret_cast<float4*>(sW)[k*32 + c4] = W4[(kc*32+k)*64 + (cb>>2) + c4];
        }
        __syncthreads();

        #pragma unroll
        for (int k=0; k<32; k++){
            float a[8];
            #pragma unroll
            for (int i=0;i<4;i++){
                a[i]   = sA[(r0+i)*SAS + k];
                a[4+i] = sA[(r0+64+i)*SAS + k];
            }
            float4 w0 = *reinterpret_cast<const float4*>(&sW[k*128 + c0]);
            float4 w1 = *reinterpret_cast<const float4*>(&sW[k*128 + c0 + 64]);
            float wv[8] = {w0.x,w0.y,w0.z,w0.w,w1.x,w1.y,w1.z,w1.w};
            #pragma unroll
            for (int i=0;i<8;i++)
                #pragma unroll
                for (int j=0;j<8;j++) acc[i][j] += a[i]*wv[j];
        }
        __syncthreads();
    }

    float4 b0 = make_float4(0.f,0.f,0.f,0.f), b1 = b0;
    if (bias){
        b0 = *reinterpret_cast<const float4*>(&bias[cb + c0]);
        b1 = *reinterpret_cast<const float4*>(&bias[cb + c0 + 64]);
    }
    #pragma unroll
    for (int i=0;i<8;i++){
        int r = row0 + ((i<4) ? (r0+i) : (64 + r0 + i - 4));
        if (r < rows){
            float4 o0 = make_float4(acc[i][0]+b0.x, acc[i][1]+b0.y, acc[i][2]+b0.z, acc[i][3]+b0.w);
            float4 o1 = make_float4(acc[i][4]+b1.x, acc[i][5]+b1.y, acc[i][6]+b1.z, acc[i][7]+b1.w);
            *reinterpret_cast<float4*>(&out[r*256 + cb + c0])      = o0;
            *reinterpret_cast<float4*>(&out[r*256 + cb + c0 + 64]) = o1;
        }
    }
}

// ---------------- edge stage A: fo = fw + ni[src] + nj[dst] + bias; scores;
//                  new f = elu(inorm(mean over heads of fo)). 4 edges/block, 64 thr/edge. ----------------
__global__ __launch_bounds__(256) void edge_a(
    const int* __restrict__ src, const int* __restrict__ dst,
    const float* __restrict__ bias_e, const float* __restrict__ attn){
    const int g = threadIdx.x >> 6;          // edge group 0..3
    const int t = threadIdx.x & 63;          // 0..63: float4 of cols 4t..4t+3
    const int e = blockIdx.x*4 + g;
    const int s = src[e], d = dst[e];

    float4 fw = reinterpret_cast<const float4*>(g_fw)[e*64 + t];
    float4 ni = reinterpret_cast<const float4*>(g_ni)[s*64 + t];
    float4 nj = reinterpret_cast<const float4*>(g_nj)[d*64 + t];
    float4 be = reinterpret_cast<const float4*>(bias_e)[t];
    float4 fo;
    fo.x = fw.x + ni.x + nj.x + be.x;
    fo.y = fw.y + ni.y + nj.y + be.y;
    fo.z = fw.z + ni.z + nj.z + be.z;
    fo.w = fw.w + ni.w + nj.w + be.w;

    float4 at = reinterpret_cast<const float4*>(attn)[t];
    float sc = (fo.x>0.f?fo.x:0.01f*fo.x)*at.x + (fo.y>0.f?fo.y:0.01f*fo.y)*at.y
             + (fo.z>0.f?fo.z:0.01f*fo.z)*at.z + (fo.w>0.f?fo.w:0.01f*fo.w)*at.w;
    #pragma unroll
    for (int o=8;o>0;o>>=1) sc += __shfl_down_sync(0xffffffffu, sc, o);
    if ((t & 15) == 0) g_score[e*4 + (t>>4)] = sc;     // head q = t>>4

    __shared__ float4 sFO[4][64];
    __shared__ float  sR[8][2];
    sFO[g][t] = fo;
    __syncthreads();

    const float* sf = reinterpret_cast<const float*>(&sFO[g][0]);
    float fm = 0.25f*(sf[t] + sf[t+64] + sf[t+128] + sf[t+192]);
    float s1 = fm, s2 = fm*fm;
    #pragma unroll
    for (int o=16;o>0;o>>=1){
        s1 += __shfl_down_sync(0xffffffffu, s1, o);
        s2 += __shfl_down_sync(0xffffffffu, s2, o);
    }
    const int w = threadIdx.x >> 5, lane = threadIdx.x & 31;
    if (lane == 0){ sR[w][0] = s1; sR[w][1] = s2; }
    __syncthreads();
    float m   = (sR[2*g][0] + sR[2*g+1][0]) * 0.015625f;
    float var = (sR[2*g][1] + sR[2*g+1][1]) * 0.015625f - m*m;
    float inv = rsqrtf(var + 1e-5f);
    float v = (fm - m) * inv;
    g_f[e*64 + t] = v > 0.f ? v : expm1f(v);
    (void)d;
}

// ---------------- fused softmax + aggregate + mean-heads + inorm + elu (per dst node) ----------------
__global__ __launch_bounds__(64) void aggregate(const int* __restrict__ src){
    const int n = blockIdx.x, t = threadIdx.x;
    const int w = t >> 5, lane = t & 31;
    const int beg = g_rowptr[n], end = g_rowptr[n+1];
    const float4* SC = reinterpret_cast<const float4*>(g_score);

    // segment max per head
    float4 mx = make_float4(-3.4e38f,-3.4e38f,-3.4e38f,-3.4e38f);
    for (int i=beg+t; i<end; i+=64){
        float4 s = SC[g_eidx[i]];
        mx.x = fmaxf(mx.x, s.x); mx.y = fmaxf(mx.y, s.y);
        mx.z = fmaxf(mx.z, s.z); mx.w = fmaxf(mx.w, s.w);
    }
    #pragma unroll
    for (int o=16;o>0;o>>=1){
        mx.x = fmaxf(mx.x, __shfl_down_sync(0xffffffffu, mx.x, o));
        mx.y = fmaxf(mx.y, __shfl_down_sync(0xffffffffu, mx.y, o));
        mx.z = fmaxf(mx.z, __shfl_down_sync(0xffffffffu, mx.z, o));
        mx.w = fmaxf(mx.w, __shfl_down_sync(0xffffffffu, mx.w, o));
    }
    __shared__ float4 sM[2];
    __shared__ float4 sD[2];
    if (lane == 0) sM[w] = mx;
    __syncthreads();
    mx.x = fmaxf(sM[0].x, sM[1].x); mx.y = fmaxf(sM[0].y, sM[1].y);
    mx.z = fmaxf(sM[0].z, sM[1].z); mx.w = fmaxf(sM[0].w, sM[1].w);

    // denominators
    float4 dn = make_float4(0.f,0.f,0.f,0.f);
    for (int i=beg+t; i<end; i+=64){
        float4 s = SC[g_eidx[i]];
        dn.x += __expf(s.x-mx.x); dn.y += __expf(s.y-mx.y);
        dn.z += __expf(s.z-mx.z); dn.w += __expf(s.w-mx.w);
    }
    #pragma unroll
    for (int o=16;o>0;o>>=1){
        dn.x += __shfl_down_sync(0xffffffffu, dn.x, o);
        dn.y += __shfl_down_sync(0xffffffffu, dn.y, o);
        dn.z += __shfl_down_sync(0xffffffffu, dn.z, o);
        dn.w += __shfl_down_sync(0xffffffffu, dn.w, o);
    }
    if (lane == 0) sD[w] = dn;
    __syncthreads();
    dn.x = sD[0].x + sD[1].x; dn.y = sD[0].y + sD[1].y;
    dn.z = sD[0].z + sD[1].z; dn.w = sD[0].w + sD[1].w;

    // weighted accumulation: thread t owns cols 4t..4t+3, head q = t>>4
    const int q = t >> 4;
    const float mq = (q==0)?mx.x:(q==1)?mx.y:(q==2)?mx.z:mx.w;
    const float dq = (q==0)?dn.x:(q==1)?dn.y:(q==2)?dn.z:dn.w;
    const float rq = (end > beg) ? 1.0f/dq : 0.f;
    float4 acc = make_float4(0.f,0.f,0.f,0.f);
    for (int i=beg; i<end; i++){
        int e = g_eidx[i];
        float a = __expf(g_score[e*4 + q] - mq) * rq;
        float4 hp = reinterpret_cast<const float4*>(g_hp)[src[e]*64 + t];
        acc.x += hp.x*a; acc.y += hp.y*a; acc.z += hp.z*a; acc.w += hp.w*a;
    }

    // mean over heads + inorm + elu
    __shared__ float sAcc[256];
    reinterpret_cast<float4*>(sAcc)[t] = acc;
    __syncthreads();
    float v = 0.25f*(sAcc[t] + sAcc[t+64] + sAcc[t+128] + sAcc[t+192]);
    float s1 = v, s2 = v*v;
    #pragma unroll
    for (int o=16;o>0;o>>=1){
        s1 += __shfl_down_sync(0xffffffffu, s1, o);
        s2 += __shfl_down_sync(0xffffffffu, s2, o);
    }
    __shared__ float sS[4];
    if (lane == 0){ sS[w] = s1; sS[2+w] = s2; }
    __syncthreads();
    float m   = (sS[0]+sS[1]) * 0.015625f;
    float var = (sS[2]+sS[3]) * 0.015625f - m*m;
    float o = (v - m) * rsqrtf(var + 1e-5f);
    g_h[n*64 + t] = o > 0.f ? o : expm1f(o);
}

// ---------------- host ----------------
extern "C" void kernel_launch(void* const* d_in, const int* in_sizes, int n_in,
                              void* d_out, int out_size){
    (void)in_sizes; (void)n_in; (void)out_size;
    const float* x      = (const float*)d_in[0];
    const float* efeat  = (const float*)d_in[1];
    const int*   src    = (const int*)  d_in[2];
    const int*   dst    = (const int*)  d_in[3];
    const float* Wn0    = (const float*)d_in[4];
    const float* bn0    = (const float*)d_in[5];
    const float* We0    = (const float*)d_in[6];
    const float* be0    = (const float*)d_in[7];
    const float* Wnode  = (const float*)d_in[8];
    const float* bnode  = (const float*)d_in[9];
    const float* Wni    = (const float*)d_in[10];
    const float* Wnj    = (const float*)d_in[11];
    const float* Wfij   = (const float*)d_in[12];
    const float* attn   = (const float*)d_in[13];
    const float* bias_e = (const float*)d_in[14];
    const float* Wf     = (const float*)d_in[15];
    const float* bf     = (const float*)d_in[16];

    float *p_h, *p_f, *p_ni, *p_nj, *p_hp, *p_fw;
    cudaGetSymbolAddress((void**)&p_h,  g_h);
    cudaGetSymbolAddress((void**)&p_f,  g_f);
    cudaGetSymbolAddress((void**)&p_ni, g_ni);
    cudaGetSymbolAddress((void**)&p_nj, g_nj);
    cudaGetSymbolAddress((void**)&p_hp, g_hp);
    cudaGetSymbolAddress((void**)&p_fw, g_fw);

    // CSR by dst (graph static within a call)
    k_zero_cnt<<<(NN+255)/256, 256>>>();
    k_count<<<(NE+255)/256, 256>>>(dst);
    k_scan<<<1, 1024>>>();
    k_scatter<<<(NE+255)/256, 256>>>(dst);

    // initial embeddings
    small_gemm<<<5000, 256>>>(x,     Wn0, bn0, p_h, NN, 65);
    small_gemm<<<8192, 256>>>(efeat, We0, be0, p_f, NE, 15);

    for (int l=0; l<2; l++){
        gemm128<<<dim3(157, 2), 256>>>(p_h, Wni   + l*16384, nullptr,       p_ni, NN);
        gemm128<<<dim3(157, 2), 256>>>(p_h, Wnj   + l*16384, nullptr,       p_nj, NN);
        gemm128<<<dim3(157, 2), 256>>>(p_h, Wnode + l*16384, bnode + l*256, p_hp, NN);
        gemm128<<<dim3(1563,2), 256>>>(p_f, Wfij  + l*16384, nullptr,       p_fw, NE);
        edge_a<<<NE/4, 256>>>(src, dst, bias_e + l*256, attn + l*256);
        aggregate<<<NN, 64>>>(src);
    }

    // final head
    small_gemm<<<5000, 256>>>(p_h, Wf, bf, (float*)d_out, NN, 64);
}

// round 4
// speedup vs baseline: 2.0390x; 1.1071x over previous
#include <cuda_runtime.h>
#include <cuda_bf16.h>
#include <math.h>
#include <stdint.h>

#define NN 20000
#define NE 200000

// ---------------- scratch (device globals; allocation-free rule) ----------------
__device__ __align__(16) float g_h[NN*64];      // node features [N,64]
__device__ __align__(16) float g_f[NE*64];      // edge features [E,64]
__device__ __align__(16) float g_ni[NN*256];    // h @ Wni   [N,256]
__device__ __align__(16) float g_nj[NN*256];    // h @ Wnj   [N,256]
__device__ __align__(16) float g_hp[NN*256];    // h @ Wnode + bnode [N,256]
__device__ __align__(16) float g_fw[NE*256];    // f @ Wfij  [E,256]
__device__ __align__(16) float g_score[NE*4];   // per-edge per-head scores
__device__ int g_rowptr[NN+1];
__device__ int g_cur[NN];
__device__ int g_eidx[NE];
// split-bf16 operands and converted weight images
__device__ __align__(16) __nv_bfloat16 g_hb[NN*128];     // [hi|lo] of h
__device__ __align__(16) __nv_bfloat16 g_fb[NE*128];     // [hi|lo] of f
__device__ __align__(16) __nv_bfloat16 g_wbuf[8*49152];  // 8 x [256 n][192 k] images

// ---------------- CSR build ----------------
__global__ void k_zero_cnt(){
    int i = blockIdx.x*blockDim.x + threadIdx.x;
    if (i < NN) g_cur[i] = 0;
}
__global__ void k_count(const int* __restrict__ dst){
    int e = blockIdx.x*blockDim.x + threadIdx.x;
    if (e < NE) atomicAdd(&g_cur[dst[e]], 1);
}
__global__ __launch_bounds__(1024) void k_scan(){
    __shared__ int sPart[1024];
    const int t = threadIdx.x;
    const int beg = t*20;
    const int end = (beg+20 < NN) ? beg+20 : NN;
    int s = 0;
    for (int i=beg; i<end; i++) s += g_cur[i];
    sPart[t] = s;
    __syncthreads();
    for (int o=1; o<1024; o<<=1){
        int v = (t >= o) ? sPart[t-o] : 0;
        __syncthreads();
        sPart[t] += v;
        __syncthreads();
    }
    int run = (t==0) ? 0 : sPart[t-1];
    for (int i=beg; i<end; i++){
        int c = g_cur[i];
        g_rowptr[i] = run;
        g_cur[i]    = run;
        run += c;
    }
    if (t == 0) g_rowptr[NN] = NE;
}
__global__ void k_scatter(const int* __restrict__ dst){
    int e = blockIdx.x*blockDim.x + threadIdx.x;
    if (e < NE){
        int p = atomicAdd(&g_cur[dst[e]], 1);
        g_eidx[p] = e;
    }
}

// ---------------- split conversions ----------------
// W' image [n][kk], kk in [0,192): kk<128 -> hi(W[kk&63][n]); kk>=128 -> lo(W[kk&63][n])
__global__ __launch_bounds__(256) void k_wconv(const float* __restrict__ W, __nv_bfloat16* __restrict__ dst){
    int idx = blockIdx.x*256 + threadIdx.x;       // 256*192 = 49152
    if (idx >= 49152) return;
    int n = idx / 192, kk = idx % 192;
    int ks = kk & 63;
    float v = W[ks*256 + n];
    __nv_bfloat16 h = __float2bfloat16(v);
    if (kk >= 128) h = __float2bfloat16(v - __bfloat162float(h));
    dst[n*192 + kk] = h;
}

// A split: in [rows,64] fp32 -> out [rows,128] bf16 as [hi|lo]
__global__ __launch_bounds__(256) void k_aconv(const float* __restrict__ in,
                                               __nv_bfloat16* __restrict__ out, int rows){
    int idx = blockIdx.x*256 + threadIdx.x;
    if (idx >= rows*64) return;
    int r = idx >> 6, c = idx & 63;
    float a = in[idx];
    __nv_bfloat16 h = __float2bfloat16(a);
    out[r*128 + c]      = h;
    out[r*128 + 64 + c] = __float2bfloat16(a - __bfloat162float(h));
}

// ---------------- bf16 HMMA GEMM: out[rows,256] = split(A) @ W' (K=192, fp32 accum) ----------------
// CTA: 128 rows x 128 cols, 256 threads = 8 warps (2 row groups x 4 col groups), warp tile 64x32.
#define MSTR 200   // smem row stride in bf16 (pad: banks r*4+lane%4 all distinct)
#define MMA_SMEM (2*128*MSTR*2)

__global__ __launch_bounds__(256) void mma_gemm(
    const __nv_bfloat16* __restrict__ ab,      // [rows,128] hi|lo
    const __nv_bfloat16* __restrict__ wimg0,   // images; mat index selects
    const float* __restrict__ bias2,           // bias for mat==2 (or null)
    float* __restrict__ o0, float* __restrict__ o1, float* __restrict__ o2,
    int rows, int nmats){
    extern __shared__ __nv_bfloat16 sm[];
    __nv_bfloat16* sA = sm;              // [128][MSTR], 192 used
    __nv_bfloat16* sW = sm + 128*MSTR;   // [128][MSTR], 192 used
    const int tid = threadIdx.x;
    const int y = blockIdx.y;
    const int mat = (nmats == 3) ? (y >> 1) : 0;
    const int ch  = (nmats == 3) ? (y & 1)  : y;
    const __nv_bfloat16* wimg = wimg0 + (size_t)mat*49152;
    float* out = (mat==0) ? o0 : (mat==1) ? o1 : o2;
    const float* bias = (mat==2) ? bias2 : nullptr;
    const int row0 = blockIdx.x*128;
    const int cb   = ch*128;

    // A cols 0..127 (hi|lo)
    #pragma unroll
    for (int it=0; it<8; it++){
        int idx = it*256 + tid;            // 0..2047
        int r = idx >> 4, c8 = (idx & 15)*8;
        uint4 v = make_uint4(0u,0u,0u,0u);
        if (row0 + r < rows) v = *reinterpret_cast<const uint4*>(ab + (size_t)(row0+r)*128 + c8);
        *reinterpret_cast<uint4*>(sA + r*MSTR + c8) = v;
    }
    // A cols 128..191 = hi replica
    #pragma unroll
    for (int it=0; it<4; it++){
        int idx = it*256 + tid;            // 0..1023
        int r = idx >> 3, c8 = (idx & 7)*8;
        uint4 v = make_uint4(0u,0u,0u,0u);
        if (row0 + r < rows) v = *reinterpret_cast<const uint4*>(ab + (size_t)(row0+r)*128 + c8);
        *reinterpret_cast<uint4*>(sA + r*MSTR + 128 + c8) = v;
    }
    // W half [cb..cb+127][0..191]
    #pragma unroll
    for (int it=0; it<12; it++){
        int idx = it*256 + tid;            // 0..3071
        int n = idx / 24, c8 = (idx % 24)*8;
        uint4 v = *reinterpret_cast<const uint4*>(wimg + (size_t)(cb+n)*192 + c8);
        *reinterpret_cast<uint4*>(sW + n*MSTR + c8) = v;
    }
    __syncthreads();

    const int wid = tid >> 5, lane = tid & 31;
    const int wrow = wid & 1, wcol = wid >> 1;
    const int lr = lane >> 2, lk2 = (lane & 3)*2;

    float acc[4][4][4];
    #pragma unroll
    for (int mi=0;mi<4;mi++)
        #pragma unroll
        for (int ni=0;ni<4;ni++)
            #pragma unroll
            for (int q=0;q<4;q++) acc[mi][ni][q] = 0.f;

    #pragma unroll
    for (int ks=0; ks<12; ks++){
        const int k = ks*16;
        uint32_t afr[4][4];
        #pragma unroll
        for (int mi=0;mi<4;mi++){
            const __nv_bfloat16* ap = sA + (wrow*64 + mi*16 + lr)*MSTR + k + lk2;
            afr[mi][0] = *reinterpret_cast<const uint32_t*>(ap);
            afr[mi][1] = *reinterpret_cast<const uint32_t*>(ap + 8*MSTR);
            afr[mi][2] = *reinterpret_cast<const uint32_t*>(ap + 8);
            afr[mi][3] = *reinterpret_cast<const uint32_t*>(ap + 8*MSTR + 8);
        }
        #pragma unroll
        for (int ni=0;ni<4;ni++){
            const __nv_bfloat16* bp = sW + (wcol*32 + ni*8 + lr)*MSTR + k + lk2;
            uint32_t b0 = *reinterpret_cast<const uint32_t*>(bp);
            uint32_t b1 = *reinterpret_cast<const uint32_t*>(bp + 8);
            #pragma unroll
            for (int mi=0;mi<4;mi++){
                asm volatile(
                    "mma.sync.aligned.m16n8k16.row.col.f32.bf16.bf16.f32 "
                    "{%0,%1,%2,%3}, {%4,%5,%6,%7}, {%8,%9}, {%0,%1,%2,%3};"
                    : "+f"(acc[mi][ni][0]), "+f"(acc[mi][ni][1]),
                      "+f"(acc[mi][ni][2]), "+f"(acc[mi][ni][3])
                    : "r"(afr[mi][0]), "r"(afr[mi][1]), "r"(afr[mi][2]), "r"(afr[mi][3]),
                      "r"(b0), "r"(b1));
            }
        }
    }

    // epilogue
    #pragma unroll
    for (int mi=0;mi<4;mi++){
        #pragma unroll
        for (int ni=0;ni<4;ni++){
            int r = row0 + wrow*64 + mi*16 + lr;
            int c = cb + wcol*32 + ni*8 + lk2;
            float bx = 0.f, by = 0.f;
            if (bias){ bx = bias[c]; by = bias[c+1]; }
            if (r < rows){
                float2 v = make_float2(acc[mi][ni][0] + bx, acc[mi][ni][1] + by);
                *reinterpret_cast<float2*>(out + (size_t)r*256 + c) = v;
            }
            if (r + 8 < rows){
                float2 v = make_float2(acc[mi][ni][2] + bx, acc[mi][ni][3] + by);
                *reinterpret_cast<float2*>(out + (size_t)(r+8)*256 + c) = v;
            }
        }
    }
}

// ---------------- generic small GEMM: out[rows,64] = A[rows,K] @ W[K,64] + bias ----------------
__global__ __launch_bounds__(256) void small_gemm(
    const float* __restrict__ A, const float* __restrict__ W,
    const float* __restrict__ bias, float* __restrict__ out, int rows, int K){
    __shared__ float sW[65*64];
    __shared__ float sA[4*65];
    for (int i=threadIdx.x; i<K*64; i+=256) sW[i] = W[i];
    __syncthreads();
    const int col = threadIdx.x & 63;
    const int rl  = threadIdx.x >> 6;
    const float b = bias[col];
    for (int base = blockIdx.x*4; base < rows; base += gridDim.x*4){
        for (int i=threadIdx.x; i<4*K; i+=256){
            int r = i / K, k = i - r*K;
            sA[i] = (base + r < rows) ? A[(base+r)*K + k] : 0.f;
        }
        __syncthreads();
        const int row = base + rl;
        if (row < rows){
            float acc = b;
            for (int k=0;k<K;k++) acc += sA[rl*K + k]*sW[k*64 + col];
            out[row*64 + col] = acc;
        }
        __syncthreads();
    }
}

// ---------------- edge stage A ----------------
__global__ __launch_bounds__(256) void edge_a(
    const int* __restrict__ src, const int* __restrict__ dst,
    const float* __restrict__ bias_e, const float* __restrict__ attn){
    const int g = threadIdx.x >> 6;
    const int t = threadIdx.x & 63;
    const int e = blockIdx.x*4 + g;
    const int s = src[e], d = dst[e];

    float4 fw = reinterpret_cast<const float4*>(g_fw)[e*64 + t];
    float4 ni = reinterpret_cast<const float4*>(g_ni)[s*64 + t];
    float4 nj = reinterpret_cast<const float4*>(g_nj)[d*64 + t];
    float4 be = reinterpret_cast<const float4*>(bias_e)[t];
    float4 fo;
    fo.x = fw.x + ni.x + nj.x + be.x;
    fo.y = fw.y + ni.y + nj.y + be.y;
    fo.z = fw.z + ni.z + nj.z + be.z;
    fo.w = fw.w + ni.w + nj.w + be.w;

    float4 at = reinterpret_cast<const float4*>(attn)[t];
    float sc = (fo.x>0.f?fo.x:0.01f*fo.x)*at.x + (fo.y>0.f?fo.y:0.01f*fo.y)*at.y
             + (fo.z>0.f?fo.z:0.01f*fo.z)*at.z + (fo.w>0.f?fo.w:0.01f*fo.w)*at.w;
    #pragma unroll
    for (int o=8;o>0;o>>=1) sc += __shfl_down_sync(0xffffffffu, sc, o);
    if ((t & 15) == 0) g_score[e*4 + (t>>4)] = sc;

    __shared__ float4 sFO[4][64];
    __shared__ float  sR[8][2];
    sFO[g][t] = fo;
    __syncthreads();

    const float* sf = reinterpret_cast<const float*>(&sFO[g][0]);
    float fm = 0.25f*(sf[t] + sf[t+64] + sf[t+128] + sf[t+192]);
    float s1 = fm, s2 = fm*fm;
    #pragma unroll
    for (int o=16;o>0;o>>=1){
        s1 += __shfl_down_sync(0xffffffffu, s1, o);
        s2 += __shfl_down_sync(0xffffffffu, s2, o);
    }
    const int w = threadIdx.x >> 5, lane = threadIdx.x & 31;
    if (lane == 0){ sR[w][0] = s1; sR[w][1] = s2; }
    __syncthreads();
    float m   = (sR[2*g][0] + sR[2*g+1][0]) * 0.015625f;
    float var = (sR[2*g][1] + sR[2*g+1][1]) * 0.015625f - m*m;
    float inv = rsqrtf(var + 1e-5f);
    float v = (fm - m) * inv;
    g_f[e*64 + t] = v > 0.f ? v : expm1f(v);
    (void)d;
}

// ---------------- fused softmax + aggregate + mean-heads + inorm + elu ----------------
__global__ __launch_bounds__(64) void aggregate(const int* __restrict__ src){
    const int n = blockIdx.x, t = threadIdx.x;
    const int w = t >> 5, lane = t & 31;
    const int beg = g_rowptr[n], end = g_rowptr[n+1];
    const float4* SC = reinterpret_cast<const float4*>(g_score);

    float4 mx = make_float4(-3.4e38f,-3.4e38f,-3.4e38f,-3.4e38f);
    for (int i=beg+t; i<end; i+=64){
        float4 s = SC[g_eidx[i]];
        mx.x = fmaxf(mx.x, s.x); mx.y = fmaxf(mx.y, s.y);
        mx.z = fmaxf(mx.z, s.z); mx.w = fmaxf(mx.w, s.w);
    }
    #pragma unroll
    for (int o=16;o>0;o>>=1){
        mx.x = fmaxf(mx.x, __shfl_down_sync(0xffffffffu, mx.x, o));
        mx.y = fmaxf(mx.y, __shfl_down_sync(0xffffffffu, mx.y, o));
        mx.z = fmaxf(mx.z, __shfl_down_sync(0xffffffffu, mx.z, o));
        mx.w = fmaxf(mx.w, __shfl_down_sync(0xffffffffu, mx.w, o));
    }
    __shared__ float4 sM[2];
    __shared__ float4 sD[2];
    if (lane == 0) sM[w] = mx;
    __syncthreads();
    mx.x = fmaxf(sM[0].x, sM[1].x); mx.y = fmaxf(sM[0].y, sM[1].y);
    mx.z = fmaxf(sM[0].z, sM[1].z); mx.w = fmaxf(sM[0].w, sM[1].w);

    float4 dn = make_float4(0.f,0.f,0.f,0.f);
    for (int i=beg+t; i<end; i+=64){
        float4 s = SC[g_eidx[i]];
        dn.x += __expf(s.x-mx.x); dn.y += __expf(s.y-mx.y);
        dn.z += __expf(s.z-mx.z); dn.w += __expf(s.w-mx.w);
    }
    #pragma unroll
    for (int o=16;o>0;o>>=1){
        dn.x += __shfl_down_sync(0xffffffffu, dn.x, o);
        dn.y += __shfl_down_sync(0xffffffffu, dn.y, o);
        dn.z += __shfl_down_sync(0xffffffffu, dn.z, o);
        dn.w += __shfl_down_sync(0xffffffffu, dn.w, o);
    }
    if (lane == 0) sD[w] = dn;
    __syncthreads();
    dn.x = sD[0].x + sD[1].x; dn.y = sD[0].y + sD[1].y;
    dn.z = sD[0].z + sD[1].z; dn.w = sD[0].w + sD[1].w;

    const int q = t >> 4;
    const float mq = (q==0)?mx.x:(q==1)?mx.y:(q==2)?mx.z:mx.w;
    const float dq = (q==0)?dn.x:(q==1)?dn.y:(q==2)?dn.z:dn.w;
    const float rq = (end > beg) ? 1.0f/dq : 0.f;
    float4 acc = make_float4(0.f,0.f,0.f,0.f);
    for (int i=beg; i<end; i++){
        int e = g_eidx[i];
        float a = __expf(g_score[e*4 + q] - mq) * rq;
        float4 hp = reinterpret_cast<const float4*>(g_hp)[src[e]*64 + t];
        acc.x += hp.x*a; acc.y += hp.y*a; acc.z += hp.z*a; acc.w += hp.w*a;
    }

    __shared__ float sAcc[256];
    reinterpret_cast<float4*>(sAcc)[t] = acc;
    __syncthreads();
    float v = 0.25f*(sAcc[t] + sAcc[t+64] + sAcc[t+128] + sAcc[t+192]);
    float s1 = v, s2 = v*v;
    #pragma unroll
    for (int o=16;o>0;o>>=1){
        s1 += __shfl_down_sync(0xffffffffu, s1, o);
        s2 += __shfl_down_sync(0xffffffffu, s2, o);
    }
    __shared__ float sS[4];
    if (lane == 0){ sS[w] = s1; sS[2+w] = s2; }
    __syncthreads();
    float m   = (sS[0]+sS[1]) * 0.015625f;
    float var = (sS[2]+sS[3]) * 0.015625f - m*m;
    float o = (v - m) * rsqrtf(var + 1e-5f);
    g_h[n*64 + t] = o > 0.f ? o : expm1f(o);
}

// ---------------- host ----------------
extern "C" void kernel_launch(void* const* d_in, const int* in_sizes, int n_in,
                              void* d_out, int out_size){
    (void)in_sizes; (void)n_in; (void)out_size;
    const float* x      = (const float*)d_in[0];
    const float* efeat  = (const float*)d_in[1];
    const int*   src    = (const int*)  d_in[2];
    const int*   dst    = (const int*)  d_in[3];
    const float* Wn0    = (const float*)d_in[4];
    const float* bn0    = (const float*)d_in[5];
    const float* We0    = (const float*)d_in[6];
    const float* be0    = (const float*)d_in[7];
    const float* Wnode  = (const float*)d_in[8];
    const float* bnode  = (const float*)d_in[9];
    const float* Wni    = (const float*)d_in[10];
    const float* Wnj    = (const float*)d_in[11];
    const float* Wfij   = (const float*)d_in[12];
    const float* attn   = (const float*)d_in[13];
    const float* bias_e = (const float*)d_in[14];
    const float* Wf     = (const float*)d_in[15];
    const float* bf     = (const float*)d_in[16];

    float *p_h, *p_f, *p_ni, *p_nj, *p_hp, *p_fw;
    __nv_bfloat16 *p_hb, *p_fb, *p_wb;
    cudaGetSymbolAddress((void**)&p_h,  g_h);
    cudaGetSymbolAddress((void**)&p_f,  g_f);
    cudaGetSymbolAddress((void**)&p_ni, g_ni);
    cudaGetSymbolAddress((void**)&p_nj, g_nj);
    cudaGetSymbolAddress((void**)&p_hp, g_hp);
    cudaGetSymbolAddress((void**)&p_fw, g_fw);
    cudaGetSymbolAddress((void**)&p_hb, g_hb);
    cudaGetSymbolAddress((void**)&p_fb, g_fb);
    cudaGetSymbolAddress((void**)&p_wb, g_wbuf);

    cudaFuncSetAttribute(mma_gemm, cudaFuncAttributeMaxDynamicSharedMemorySize, MMA_SMEM);

    // weight images (layer-major: [l*4 + {ni,nj,node,fij}])
    for (int l=0; l<2; l++){
        k_wconv<<<192, 256>>>(Wni   + l*16384, p_wb + (size_t)(l*4+0)*49152);
        k_wconv<<<192, 256>>>(Wnj   + l*16384, p_wb + (size_t)(l*4+1)*49152);
        k_wconv<<<192, 256>>>(Wnode + l*16384, p_wb + (size_t)(l*4+2)*49152);
        k_wconv<<<192, 256>>>(Wfij  + l*16384, p_wb + (size_t)(l*4+3)*49152);
    }

    // CSR by dst
    k_zero_cnt<<<(NN+255)/256, 256>>>();
    k_count<<<(NE+255)/256, 256>>>(dst);
    k_scan<<<1, 1024>>>();
    k_scatter<<<(NE+255)/256, 256>>>(dst);

    // initial embeddings
    small_gemm<<<5000, 256>>>(x,     Wn0, bn0, p_h, NN, 65);
    small_gemm<<<8192, 256>>>(efeat, We0, be0, p_f, NE, 15);

    for (int l=0; l<2; l++){
        k_aconv<<<(NN*64+255)/256, 256>>>(p_h, p_hb, NN);
        k_aconv<<<(NE*64+255)/256, 256>>>(p_f, p_fb, NE);
        // node: ni/nj/hp (3 mats x 2 col-halves); edge: fij (2 col-halves)
        mma_gemm<<<dim3(157, 6), 256, MMA_SMEM>>>(
            p_hb, p_wb + (size_t)(l*4+0)*49152, bnode + l*256, p_ni, p_nj, p_hp, NN, 3);
        mma_gemm<<<dim3(1563, 2), 256, MMA_SMEM>>>(
            p_fb, p_wb + (size_t)(l*4+3)*49152, nullptr, p_fw, p_fw, p_fw, NE, 1);
        edge_a<<<NE/4, 256>>>(src, dst, bias_e + l*256, attn + l*256);
        aggregate<<<NN, 64>>>(src);
    }

    // final head
    small_gemm<<<5000, 256>>>(p_h, Wf, bf, (float*)d_out, NN, 64);
}